// round 2
// baseline (speedup 1.0000x reference)
#include <cuda_runtime.h>
#include <mma.h>
#include <cstdint>

using namespace nvcuda;

#define B_   1024
#define H_   512
#define E_   256
#define S_   128
#define T_   128
#define V_   128
#define G4   2048            // 4*H
#define KPAD 800             // 256(x) + 512(h) + 1(bias) padded to multiple of 32
#define ZLD  40              // smem leading dim (pad to dodge conflicts)

// ---------------- scratch (device globals; no allocation allowed) ----------------
__device__ float g_Wenc[(long)G4 * KPAD];            // [wih | whh | bih+bhh | 0...] tf32-rounded
__device__ float g_Wdec[(long)G4 * KPAD];
__device__ float g_fcw[(long)V_ * H_];               // tf32-rounded fc_w
__device__ float g_biasfc[16 * V_];                  // fc_b replicated over 16 rows (acc-frag init)
__device__ float g_h[2][(long)B_ * H_];              // double-buffered hidden state
__device__ float g_c[2][(long)B_ * H_];              // double-buffered cell state
__device__ float g_hseq[(long)B_ * (T_ - 1) * H_];   // decoder h outputs (266 MB)
__device__ float g_logits[(long)B_ * (T_ - 1) * V_]; // FC outputs before scatter (66 MB)

__device__ __forceinline__ float sigm(float x) { return 1.f / (1.f + __expf(-x)); }

// ---------------- prep: build combined weights (tf32-rounded), bias tile, zero h0/c0 ----------------
__global__ void prep_kernel(
    const float* __restrict__ enc_wih, const float* __restrict__ enc_whh,
    const float* __restrict__ enc_bih, const float* __restrict__ enc_bhh,
    const float* __restrict__ dec_wih, const float* __restrict__ dec_whh,
    const float* __restrict__ dec_bih, const float* __restrict__ dec_bhh,
    const float* __restrict__ fc_w,    const float* __restrict__ fc_b)
{
    const long NW   = (long)G4 * KPAD;
    const long NFCW = (long)V_ * H_;
    const long NBF  = 16L * V_;
    const long NHC  = (long)B_ * H_;
    const long total = 2 * NW + NFCW + NBF + 2 * NHC;
    for (long i = (long)blockIdx.x * blockDim.x + threadIdx.x; i < total;
         i += (long)gridDim.x * blockDim.x) {
        long r = i;
        if (r < 2 * NW) {
            bool dec = r >= NW;
            long j = dec ? r - NW : r;
            int n = (int)(j / KPAD);
            int k = (int)(j % KPAD);
            const float* wih = dec ? dec_wih : enc_wih;
            const float* whh = dec ? dec_whh : enc_whh;
            const float* bih = dec ? dec_bih : enc_bih;
            const float* bhh = dec ? dec_bhh : enc_bhh;
            float v;
            if (k < E_)            v = wih[(long)n * E_ + k];
            else if (k < E_ + H_)  v = whh[(long)n * H_ + (k - E_)];
            else if (k == E_ + H_) v = bih[n] + bhh[n];
            else                   v = 0.f;
            (dec ? g_Wdec : g_Wenc)[j] = wmma::__float_to_tf32(v);
        } else if (r < 2 * NW + NFCW) {
            long j = r - 2 * NW;
            g_fcw[j] = wmma::__float_to_tf32(fc_w[j]);
        } else if (r < 2 * NW + NFCW + NBF) {
            long j = r - 2 * NW - NFCW;
            g_biasfc[j] = fc_b[j % V_];
        } else {
            long j = r - 2 * NW - NFCW - NBF;
            if (j < NHC) g_h[0][j] = 0.f;
            else         g_c[0][j - NHC] = 0.f;
        }
    }
}

// ---------------- one LSTM step: gather x, fused [x|h|1] @ W^T, LSTM cell, all in one kernel ----------------
// Orientation: A = W rows (gate outputs), B = z^T (batch columns). acc is (j x b).
// Each warp owns 16 j's x 32 b's for ALL FOUR gates -> register-resident cell update
// (accumulator fragments of identical type have identical element<->coord mapping).
__global__ __launch_bounds__(256, 1) void step_kernel(
    const int* __restrict__ tok, const float* __restrict__ table,
    int t, int parity, int is_dec)
{
    const float* __restrict__ W      = is_dec ? g_Wdec : g_Wenc;
    const float* __restrict__ h_prev = g_h[parity];
    const float* __restrict__ c_prev = g_c[parity];
    float* __restrict__ h_next = g_h[parity ^ 1];
    float* __restrict__ c_next = g_c[parity ^ 1];

    __shared__ __align__(16) float zs[64][ZLD];   // z chunk: 64 batch rows x 32 k (tf32-rounded)

    const int tid    = threadIdx.x;
    const int warp   = tid >> 5;
    const int warp_j = warp & 3;                  // 4 warps along j (16 each)
    const int warp_b = warp >> 2;                 // 2 warps along batch (32 each)
    const int j0w = blockIdx.y * 64 + warp_j * 16;
    const int b0w = blockIdx.x * 64 + warp_b * 32;

    // staging assignment: each thread = one batch row r, 8 consecutive k's
    const int r  = tid >> 2;
    const int kq = tid & 3;
    const int gb = blockIdx.x * 64 + r;
    const int tok_idx = tok[(long)gb * S_ + t];
    const float* __restrict__ xrow = table + (long)tok_idx * E_;
    const float* __restrict__ hrow = h_prev + (long)gb * H_;

    wmma::fragment<wmma::accumulator, 16, 16, 8, float> acc[4][2];
    #pragma unroll
    for (int g = 0; g < 4; g++)
        #pragma unroll
        for (int cb = 0; cb < 2; cb++)
            wmma::fill_fragment(acc[g][cb], 0.f);

    for (int ch = 0; ch < KPAD / 32; ch++) {
        const int k0 = ch * 32 + kq * 8;
        #pragma unroll
        for (int jj = 0; jj < 8; jj++) {
            int k = k0 + jj;
            float v;
            if (k < E_)            v = xrow[k];
            else if (k < E_ + H_)  v = hrow[k - E_];
            else                   v = (k == E_ + H_) ? 1.f : 0.f;   // folded-bias ones column
            zs[r][kq * 8 + jj] = wmma::__float_to_tf32(v);
        }
        __syncthreads();
        #pragma unroll
        for (int kk = 0; kk < 4; kk++) {
            wmma::fragment<wmma::matrix_b, 16, 16, 8, wmma::precision::tf32, wmma::col_major> bfr[2];
            #pragma unroll
            for (int cb = 0; cb < 2; cb++)
                wmma::load_matrix_sync(bfr[cb], &zs[warp_b * 32 + cb * 16][kk * 8], ZLD);
            #pragma unroll
            for (int g = 0; g < 4; g++) {
                wmma::fragment<wmma::matrix_a, 16, 16, 8, wmma::precision::tf32, wmma::row_major> afr;
                wmma::load_matrix_sync(afr, W + (long)(g * H_ + j0w) * KPAD + ch * 32 + kk * 8, KPAD);
                #pragma unroll
                for (int cb = 0; cb < 2; cb++)
                    wmma::mma_sync(acc[g][cb], afr, bfr[cb], acc[g][cb]);
            }
        }
        __syncthreads();
    }

    // Epilogue: LSTM cell, fully register-resident per warp
    #pragma unroll
    for (int cb = 0; cb < 2; cb++) {
        const int bb = b0w + cb * 16;
        wmma::fragment<wmma::accumulator, 16, 16, 8, float> cp, hn, cn;
        // acc is (row=j, col=b); memory h/c is [b][j] -> col_major with ld = H
        wmma::load_matrix_sync(cp, c_prev + (long)bb * H_ + j0w, H_, wmma::mem_col_major);
        #pragma unroll
        for (int e = 0; e < 8; e++) {
            float ig = sigm(acc[0][cb].x[e]);
            float fg = sigm(acc[1][cb].x[e]);
            float gg = tanhf(acc[2][cb].x[e]);
            float og = sigm(acc[3][cb].x[e]);
            float cN = fg * cp.x[e] + ig * gg;
            cn.x[e] = cN;
            hn.x[e] = og * tanhf(cN);
        }
        wmma::store_matrix_sync(c_next + (long)bb * H_ + j0w, cn, H_, wmma::mem_col_major);
        wmma::store_matrix_sync(h_next + (long)bb * H_ + j0w, hn, H_, wmma::mem_col_major);
        if (is_dec)
            wmma::store_matrix_sync(g_hseq + (long)bb * ((T_ - 1) * H_) + (long)t * H_ + j0w,
                                    hn, (T_ - 1) * H_, wmma::mem_col_major);
    }
}

// ---------------- FC head: logits = h_seq @ fc_w^T + fc_b  (M=130048, N=128, K=512) ----------------
__global__ __launch_bounds__(256, 1) void fc_kernel()
{
    __shared__ __align__(16) float as[64][ZLD];
    const int tid    = threadIdx.x;
    const int warp   = tid >> 5;
    const int warp_m = warp & 3;
    const int warp_n = warp >> 2;
    const long R0 = (long)blockIdx.x * 64;
    const int  n0 = blockIdx.y * 64 + warp_n * 32;

    const int r  = tid >> 2;
    const int kq = tid & 3;
    const float* __restrict__ arow = g_hseq + (R0 + r) * H_;

    wmma::fragment<wmma::accumulator, 16, 16, 8, float> acc[2];
    #pragma unroll
    for (int cb = 0; cb < 2; cb++)
        wmma::load_matrix_sync(acc[cb], g_biasfc + n0 + cb * 16, V_, wmma::mem_row_major);

    for (int ch = 0; ch < H_ / 32; ch++) {
        const int k0 = ch * 32 + kq * 8;
        #pragma unroll
        for (int jj = 0; jj < 8; jj++)
            as[r][kq * 8 + jj] = wmma::__float_to_tf32(arow[k0 + jj]);
        __syncthreads();
        #pragma unroll
        for (int kk = 0; kk < 4; kk++) {
            wmma::fragment<wmma::matrix_a, 16, 16, 8, wmma::precision::tf32, wmma::row_major> afr;
            wmma::load_matrix_sync(afr, &as[warp_m * 16][kk * 8], ZLD);
            #pragma unroll
            for (int cb = 0; cb < 2; cb++) {
                wmma::fragment<wmma::matrix_b, 16, 16, 8, wmma::precision::tf32, wmma::col_major> bfr;
                wmma::load_matrix_sync(bfr, g_fcw + (long)(n0 + cb * 16) * H_ + ch * 32 + kk * 8, H_);
                wmma::mma_sync(acc[cb], afr, bfr, acc[cb]);
            }
        }
        __syncthreads();
    }
    const long Rw = R0 + warp_m * 16;
    #pragma unroll
    for (int cb = 0; cb < 2; cb++)
        wmma::store_matrix_sync(g_logits + Rw * V_ + n0 + cb * 16, acc[cb], V_, wmma::mem_row_major);
}

// ---------------- scatter logits into (B, T, V) with zero row at t=0 ----------------
__global__ void out_kernel(float* __restrict__ out)
{
    const long n4 = (long)B_ * T_ * V_ / 4;
    for (long i = (long)blockIdx.x * blockDim.x + threadIdx.x; i < n4;
         i += (long)gridDim.x * blockDim.x) {
        long e = i * 4;
        int  v  = (int)(e % V_);
        long bt = e / V_;
        int  tt = (int)(bt % T_);
        long b  = bt / T_;
        float4 val;
        if (tt == 0) val = make_float4(0.f, 0.f, 0.f, 0.f);
        else val = *reinterpret_cast<const float4*>(
                       &g_logits[(b * (T_ - 1) + (tt - 1)) * V_ + v]);
        reinterpret_cast<float4*>(out)[i] = val;
    }
}

// ---------------- launch ----------------
extern "C" void kernel_launch(void* const* d_in, const int* in_sizes, int n_in,
                              void* d_out, int out_size)
{
    (void)in_sizes; (void)n_in; (void)out_size;
    const int*   src      = (const int*)  d_in[0];
    const int*   target   = (const int*)  d_in[1];
    const float* emb      = (const float*)d_in[2];
    const float* dec_emb  = (const float*)d_in[3];
    const float* enc_wih  = (const float*)d_in[4];
    const float* enc_whh  = (const float*)d_in[5];
    const float* enc_bih  = (const float*)d_in[6];
    const float* enc_bhh  = (const float*)d_in[7];
    const float* dec_wih  = (const float*)d_in[8];
    const float* dec_whh  = (const float*)d_in[9];
    const float* dec_bih  = (const float*)d_in[10];
    const float* dec_bhh  = (const float*)d_in[11];
    const float* fc_w     = (const float*)d_in[12];
    const float* fc_b     = (const float*)d_in[13];
    float* out = (float*)d_out;

    prep_kernel<<<2048, 256>>>(enc_wih, enc_whh, enc_bih, enc_bhh,
                               dec_wih, dec_whh, dec_bih, dec_bhh,
                               fc_w, fc_b);

    int s = 0;
    for (int t = 0; t < S_; ++t, ++s)          // encoder: 128 steps
        step_kernel<<<dim3(16, 8), 256>>>(src, emb, t, s & 1, 0);
    for (int t = 0; t < T_ - 1; ++t, ++s)      // decoder: 127 steps
        step_kernel<<<dim3(16, 8), 256>>>(target, dec_emb, t, s & 1, 1);

    fc_kernel<<<dim3((B_ * (T_ - 1)) / 64, V_ / 64), 256>>>();
    out_kernel<<<2048, 256>>>(out);
}

// round 3
// speedup vs baseline: 4.5215x; 4.5215x over previous
#include <cuda_runtime.h>
#include <cuda_fp16.h>
#include <mma.h>
#include <cstdint>

using namespace nvcuda;

#define B_   1024
#define H_   512
#define E_   256
#define S_   128
#define T_   128
#define V_   128
#define G4   2048
#define JT_  16          // j-tiles (each = 32 h-dims x 4 gates = 128 gate rows)
#define CTAB 128         // batch cols per CTA
#define LDH  520         // smem ld for h / fc_w tiles (halves) -> 1040B rows, conflict-free
#define LDW  72          // smem ld for streamed A/W chunks (halves) -> 144B rows
#define SMEM_BYTES (128*LDH*2 + 2*128*LDW*2)   // 133120 + 36864 = 169984

// ---------------- device scratch ----------------
__device__ __half g_W2[2][JT_ * 128 * H_];           // reordered whh fp16: [jt][g*32+h][k]
__device__ float  g_embp[2][(long)V_ * G4];          // emb @ wih^T + bih + bhh (exact fp32)
__device__ __half g_fcw16[V_ * H_];                  // fc_w fp16 [n][k]
__device__ float  g_biasfc[16 * V_];                 // fc_b replicated 16 rows
__device__ __half g_hf[2][(long)B_ * H_];            // hidden state fp16, double buffered
__device__ float  g_c[2][(long)B_ * H_];             // cell state fp32, double buffered
__device__ __half g_hseq[(long)B_ * (T_ - 1) * H_];  // decoder h outputs fp16
__device__ float  g_logits[(long)B_ * (T_ - 1) * V_];

__device__ __forceinline__ float sigm(float x) { return 1.f / (1.f + __expf(-x)); }

__device__ __forceinline__ void cpa16(void* dst, const void* src) {
    unsigned d = (unsigned)__cvta_generic_to_shared(dst);
    asm volatile("cp.async.cg.shared.global [%0], [%1], 16;\n" :: "r"(d), "l"(src));
}
#define CPC()  asm volatile("cp.async.commit_group;\n" ::: "memory")
#define CPW(n) asm volatile("cp.async.wait_group %0;\n" :: "n"(n) : "memory")

// ---------------- prep A: embproj = emb @ wih^T + bih + bhh (exact fp32) ----------------
__global__ void prep_embproj(const float* __restrict__ emb, const float* __restrict__ wih,
                             const float* __restrict__ bih, const float* __restrict__ bhh,
                             int is_dec)
{
    __shared__ float er[E_];
    int v = blockIdx.x;
    int n = blockIdx.y * 256 + threadIdx.x;
    er[threadIdx.x] = emb[(long)v * E_ + threadIdx.x];
    __syncthreads();
    float s = bih[n] + bhh[n];
    const float* wr = wih + (long)n * E_;
    #pragma unroll 8
    for (int k = 0; k < E_; k++) s += er[k] * wr[k];
    g_embp[is_dec][(long)v * G4 + n] = s;
}

// ---------------- prep B: reorder whh to fp16, fc weights, bias tile, zero states --------
__global__ void prep2(const float* __restrict__ enc_whh, const float* __restrict__ dec_whh,
                      const float* __restrict__ fc_w,    const float* __restrict__ fc_b)
{
    const long NW  = (long)JT_ * 128 * H_;           // per direction
    const long NFC = (long)V_ * H_;
    const long NB  = 16L * V_;
    const long NS  = (long)B_ * H_;
    const long total = 2 * NW + NFC + NB + 2 * NS;
    for (long i = (long)blockIdx.x * blockDim.x + threadIdx.x; i < total;
         i += (long)gridDim.x * blockDim.x) {
        long r = i;
        if (r < 2 * NW) {
            int ed = (int)(r / NW);
            long l = r % NW;
            int jt = (int)(l / (128L * H_));
            int rr = (int)((l / H_) % 128);
            int k  = (int)(l % H_);
            int g = rr >> 5, hh = rr & 31;
            long n = (long)g * H_ + jt * 32 + hh;
            const float* whh = ed ? dec_whh : enc_whh;
            g_W2[ed][l] = __float2half(whh[n * H_ + k]);
        } else if (r < 2 * NW + NFC) {
            long l = r - 2 * NW;
            g_fcw16[l] = __float2half(fc_w[l]);
        } else if (r < 2 * NW + NFC + NB) {
            long l = r - 2 * NW - NFC;
            g_biasfc[l] = fc_b[l % V_];
        } else {
            long l = r - 2 * NW - NFC - NB;
            if (l < NS) g_hf[0][l] = __float2half(0.f);
            else        g_c[0][l - NS] = 0.f;
        }
    }
}

// ---------------- one LSTM step: gates = embproj[tok] + h @ whh^T ; cell update ----------
// CTA: 32 h-dims (x4 gates = 128 gate rows) x 128 batch. grid = (8 btiles, 16 jtiles).
// h tile fully SMEM-resident (fp16), W streamed with cp.async double buffering.
__global__ __launch_bounds__(256, 1) void step_kernel(
    const int* __restrict__ tok, int tok_stride, int t, int par, int is_dec)
{
    extern __shared__ __align__(16) char smem[];
    __half* h_s = (__half*)smem;                                   // [128 b][LDH k]
    __half* wb0 = (__half*)(smem + 128 * LDH * 2);                 // [128 row][LDW]
    __half* wb1 = (__half*)(smem + 128 * LDH * 2 + 128 * LDW * 2);
    __shared__ int tok_s[CTAB];

    const int tid = threadIdx.x;
    const int warp = tid >> 5;
    const int wj = warp & 1;          // 2 warps along h (16 h each)
    const int wbt = warp >> 1;        // 4 warps along batch (32 b each)
    const int b0 = blockIdx.x * CTAB;
    const int jt = blockIdx.y;

    const __half* __restrict__ Wg = g_W2[is_dec] + (long)jt * 128 * H_;
    const __half* __restrict__ hg = g_hf[par];

    if (tid < CTAB) tok_s[tid] = tok[(long)(b0 + tid) * tok_stride + t];

    // preload full h tile + W chunk 0 (group 0), W chunk 1 (group 1)
    for (int i = tid; i < 128 * 64; i += 256) {
        int r = i >> 6, q = i & 63;
        cpa16(h_s + r * LDH + q * 8, hg + (long)(b0 + r) * H_ + q * 8);
    }
    for (int i = tid; i < 128 * 8; i += 256) {
        int r = i >> 3, q = i & 7;
        cpa16(wb0 + r * LDW + q * 8, Wg + (long)r * H_ + q * 8);
    }
    CPC();
    for (int i = tid; i < 128 * 8; i += 256) {
        int r = i >> 3, q = i & 7;
        cpa16(wb1 + r * LDW + q * 8, Wg + (long)r * H_ + 64 + q * 8);
    }
    CPC();
    CPW(1);
    __syncthreads();

    wmma::fragment<wmma::accumulator, 16, 16, 16, float> acc[4][2];
    #pragma unroll
    for (int g = 0; g < 4; g++)
        #pragma unroll
        for (int cb = 0; cb < 2; cb++)
            wmma::fill_fragment(acc[g][cb], 0.f);

    #pragma unroll 1
    for (int ch = 0; ch < 8; ch++) {
        const __half* cw = (ch & 1) ? wb1 : wb0;
        #pragma unroll
        for (int kk = 0; kk < 4; kk++) {
            wmma::fragment<wmma::matrix_b, 16, 16, 16, half, wmma::col_major> bf[2];
            #pragma unroll
            for (int cb = 0; cb < 2; cb++)
                wmma::load_matrix_sync(bf[cb], h_s + (wbt * 32 + cb * 16) * LDH + ch * 64 + kk * 16, LDH);
            #pragma unroll
            for (int g = 0; g < 4; g++) {
                wmma::fragment<wmma::matrix_a, 16, 16, 16, half, wmma::row_major> af;
                wmma::load_matrix_sync(af, cw + (g * 32 + wj * 16) * LDW + kk * 16, LDW);
                wmma::mma_sync(acc[g][0], af, bf[0], acc[g][0]);
                wmma::mma_sync(acc[g][1], af, bf[1], acc[g][1]);
            }
        }
        __syncthreads();   // all warps done reading buffer cw
        if (ch + 2 < 8) {
            __half* nb = (ch & 1) ? wb1 : wb0;
            for (int i = tid; i < 128 * 8; i += 256) {
                int r = i >> 3, q = i & 7;
                cpa16(nb + r * LDW + q * 8, Wg + (long)r * H_ + (ch + 2) * 64 + q * 8);
            }
            CPC();
        }
        if (ch + 1 < 8) {
            if (ch + 2 < 8) { CPW(1); } else { CPW(0); }
            __syncthreads();
        }
    }

    // -------- epilogue: gather embproj, LSTM cell, store h (fp16) / c (fp32) --------
    __syncthreads();
    float* xs   = (float*)smem;                 // [128 b][132 j]  (reuses h_s)
    float* hout = (float*)(smem + 69632);       // [128 b][36 h]
    const float* __restrict__ EP = g_embp[is_dec];
    for (int i = tid; i < 128 * 128; i += 256) {
        int b = i >> 7, j = i & 127;
        int g = j >> 5, hh = j & 31;
        xs[b * 132 + j] = EP[(long)tok_s[b] * G4 + (long)g * H_ + jt * 32 + hh];
    }
    __syncthreads();

    const float* __restrict__ cp_g = g_c[par];
    float* __restrict__ cn_g = g_c[par ^ 1];
    #pragma unroll
    for (int cb = 0; cb < 2; cb++) {
        const int bl = wbt * 32 + cb * 16;
        const long cbase = (long)(b0 + bl) * H_ + jt * 32 + wj * 16;
        wmma::fragment<wmma::accumulator, 16, 16, 16, float> xf[4], cf, hn, cn;
        #pragma unroll
        for (int g = 0; g < 4; g++)
            wmma::load_matrix_sync(xf[g], xs + bl * 132 + g * 32 + wj * 16, 132, wmma::mem_col_major);
        wmma::load_matrix_sync(cf, cp_g + cbase, H_, wmma::mem_col_major);
        #pragma unroll
        for (int e = 0; e < 8; e++) {
            float ig = sigm(acc[0][cb].x[e] + xf[0].x[e]);
            float fg = sigm(acc[1][cb].x[e] + xf[1].x[e]);
            float gg = tanhf(acc[2][cb].x[e] + xf[2].x[e]);
            float og = sigm(acc[3][cb].x[e] + xf[3].x[e]);
            float c2 = fg * cf.x[e] + ig * gg;
            cn.x[e] = c2;
            hn.x[e] = og * tanhf(c2);
        }
        wmma::store_matrix_sync(cn_g + cbase, cn, H_, wmma::mem_col_major);
        wmma::store_matrix_sync(hout + bl * 36 + wj * 16, hn, 36, wmma::mem_col_major);
    }
    __syncthreads();

    __half* __restrict__ hg2 = g_hf[par ^ 1];
    for (int i = tid; i < 128 * 32; i += 256) {
        int b = i >> 5, hh = i & 31;
        __half v = __float2half(hout[b * 36 + hh]);
        hg2[(long)(b0 + b) * H_ + jt * 32 + hh] = v;
        if (is_dec)
            g_hseq[((long)(b0 + b) * (T_ - 1) + t) * H_ + jt * 32 + hh] = v;
    }
}

// ---------------- FC head: logits = h_seq @ fc_w^T + fc_b  (fp16 in, fp32 acc) ----------
__global__ __launch_bounds__(256, 1) void fc_kernel()
{
    extern __shared__ __align__(16) char smem[];
    __half* bsm = (__half*)smem;                                   // fc_w [128 n][LDH k]
    __half* ab0 = (__half*)(smem + 128 * LDH * 2);
    __half* ab1 = (__half*)(smem + 128 * LDH * 2 + 128 * LDW * 2);

    const int tid = threadIdx.x;
    const int warp = tid >> 5;
    const int wm = warp >> 2;       // 2 warps along m (64 each)
    const int wn = warp & 3;        // 4 warps along n (32 each)
    const long m0 = (long)blockIdx.x * 128;

    // load full fc_w (group 0 with A chunk 0), A chunk 1 (group 1)
    for (int i = tid; i < 128 * 64; i += 256) {
        int r = i >> 6, q = i & 63;
        cpa16(bsm + r * LDH + q * 8, g_fcw16 + (long)r * H_ + q * 8);
    }
    for (int i = tid; i < 128 * 8; i += 256) {
        int r = i >> 3, q = i & 7;
        cpa16(ab0 + r * LDW + q * 8, g_hseq + (m0 + r) * H_ + q * 8);
    }
    CPC();
    for (int i = tid; i < 128 * 8; i += 256) {
        int r = i >> 3, q = i & 7;
        cpa16(ab1 + r * LDW + q * 8, g_hseq + (m0 + r) * H_ + 64 + q * 8);
    }
    CPC();
    CPW(1);
    __syncthreads();

    wmma::fragment<wmma::accumulator, 16, 16, 16, float> acc[4][2];
    #pragma unroll
    for (int mm = 0; mm < 4; mm++)
        #pragma unroll
        for (int cb = 0; cb < 2; cb++)
            wmma::load_matrix_sync(acc[mm][cb], g_biasfc + wn * 32 + cb * 16, V_, wmma::mem_row_major);

    #pragma unroll 1
    for (int ch = 0; ch < 8; ch++) {
        const __half* ca = (ch & 1) ? ab1 : ab0;
        #pragma unroll
        for (int kk = 0; kk < 4; kk++) {
            wmma::fragment<wmma::matrix_b, 16, 16, 16, half, wmma::col_major> bf[2];
            #pragma unroll
            for (int cb = 0; cb < 2; cb++)
                wmma::load_matrix_sync(bf[cb], bsm + (wn * 32 + cb * 16) * LDH + ch * 64 + kk * 16, LDH);
            #pragma unroll
            for (int mm = 0; mm < 4; mm++) {
                wmma::fragment<wmma::matrix_a, 16, 16, 16, half, wmma::row_major> af;
                wmma::load_matrix_sync(af, ca + (wm * 64 + mm * 16) * LDW + kk * 16, LDW);
                wmma::mma_sync(acc[mm][0], af, bf[0], acc[mm][0]);
                wmma::mma_sync(acc[mm][1], af, bf[1], acc[mm][1]);
            }
        }
        __syncthreads();
        if (ch + 2 < 8) {
            __half* nb = (ch & 1) ? ab1 : ab0;
            for (int i = tid; i < 128 * 8; i += 256) {
                int r = i >> 3, q = i & 7;
                cpa16(nb + r * LDW + q * 8, g_hseq + (m0 + r) * H_ + (ch + 2) * 64 + q * 8);
            }
            CPC();
        }
        if (ch + 1 < 8) {
            if (ch + 2 < 8) { CPW(1); } else { CPW(0); }
            __syncthreads();
        }
    }

    #pragma unroll
    for (int mm = 0; mm < 4; mm++)
        #pragma unroll
        for (int cb = 0; cb < 2; cb++)
            wmma::store_matrix_sync(g_logits + (m0 + wm * 64 + mm * 16) * V_ + wn * 32 + cb * 16,
                                    acc[mm][cb], V_, wmma::mem_row_major);
}

// ---------------- scatter logits into (B, T, V) with zero row at t=0 ----------------
__global__ void out_kernel(float* __restrict__ out)
{
    const long n4 = (long)B_ * T_ * V_ / 4;
    for (long i = (long)blockIdx.x * blockDim.x + threadIdx.x; i < n4;
         i += (long)gridDim.x * blockDim.x) {
        long e = i * 4;
        int  v  = (int)(e % V_);
        long bt = e / V_;
        int  tt = (int)(bt % T_);
        long b  = bt / T_;
        float4 val;
        if (tt == 0) val = make_float4(0.f, 0.f, 0.f, 0.f);
        else val = *reinterpret_cast<const float4*>(
                       &g_logits[(b * (T_ - 1) + (tt - 1)) * V_ + v]);
        reinterpret_cast<float4*>(out)[i] = val;
    }
}

// ---------------- launch ----------------
extern "C" void kernel_launch(void* const* d_in, const int* in_sizes, int n_in,
                              void* d_out, int out_size)
{
    (void)in_sizes; (void)n_in; (void)out_size;
    const int*   src      = (const int*)  d_in[0];
    const int*   target   = (const int*)  d_in[1];
    const float* emb      = (const float*)d_in[2];
    const float* dec_emb  = (const float*)d_in[3];
    const float* enc_wih  = (const float*)d_in[4];
    const float* enc_whh  = (const float*)d_in[5];
    const float* enc_bih  = (const float*)d_in[6];
    const float* enc_bhh  = (const float*)d_in[7];
    const float* dec_wih  = (const float*)d_in[8];
    const float* dec_whh  = (const float*)d_in[9];
    const float* dec_bih  = (const float*)d_in[10];
    const float* dec_bhh  = (const float*)d_in[11];
    const float* fc_w     = (const float*)d_in[12];
    const float* fc_b     = (const float*)d_in[13];
    float* out = (float*)d_out;

    cudaFuncSetAttribute(step_kernel, cudaFuncAttributeMaxDynamicSharedMemorySize, SMEM_BYTES);
    cudaFuncSetAttribute(fc_kernel,   cudaFuncAttributeMaxDynamicSharedMemorySize, SMEM_BYTES);

    prep_embproj<<<dim3(V_, G4 / 256), 256>>>(emb,     enc_wih, enc_bih, enc_bhh, 0);
    prep_embproj<<<dim3(V_, G4 / 256), 256>>>(dec_emb, dec_wih, dec_bih, dec_bhh, 1);
    prep2<<<2048, 256>>>(enc_whh, dec_whh, fc_w, fc_b);

    int s = 0;
    for (int t = 0; t < S_; ++t, ++s)
        step_kernel<<<dim3(B_ / CTAB, JT_), 256, SMEM_BYTES>>>(src, S_, t, s & 1, 0);
    for (int t = 0; t < T_ - 1; ++t, ++s)
        step_kernel<<<dim3(B_ / CTAB, JT_), 256, SMEM_BYTES>>>(target, T_, t, s & 1, 1);

    fc_kernel<<<(B_ * (T_ - 1)) / 128, 256, SMEM_BYTES>>>();
    out_kernel<<<2048, 256>>>(out);
}

// round 4
// speedup vs baseline: 4.5905x; 1.0153x over previous
#include <cuda_runtime.h>
#include <cuda_fp16.h>
#include <mma.h>
#include <cstdint>

using namespace nvcuda;

#define B_   1024
#define H_   512
#define E_   256
#define S_   128
#define T_   128
#define V_   128
#define G4   2048
#define JT_  16
#define NCTA 128
#define NSTEP (S_ + T_ - 1)     // 255
#define LDH  520                // smem ld (halves) for resident W / fc_w: 1040B rows
#define LDW  72                 // smem ld (halves) for streamed chunks: 144B rows
#define WBYTES   (128 * LDH * 2)                 // 133120: resident W tile
#define EPI_XS   (128 * 132 * 4)                 // 67584: xs fp32
#define EPI_HO   (128 * 36 * 4)                  // 18432: hout fp32
#define SEQ_SMEM (WBYTES + EPI_XS + EPI_HO)      // 219136
#define FC_SMEM  (128 * LDH * 2 + 2 * 128 * LDW * 2)  // 169984

// ---------------- device scratch ----------------
__device__ __half g_W2[2][JT_ * 128 * H_];           // reordered whh fp16: [jt][g*32+h][k]
__device__ float  g_embp[2][(long)V_ * G4];          // emb @ wih^T + bih + bhh (exact fp32)
__device__ __half g_fcw16[V_ * H_];
__device__ float  g_biasfc[16 * V_];
__device__ __half g_hf[2][(long)B_ * H_];            // hidden fp16, double buffered (cross-CTA via L2)
__device__ float  g_c[2][(long)B_ * H_];             // cell fp32, double buffered (CTA-private tiles)
__device__ __half g_hseq[(long)B_ * (T_ - 1) * H_];
__device__ float  g_logits[(long)B_ * (T_ - 1) * V_];
__device__ unsigned g_bar;                           // grid barrier counter (reset by prep2)

__device__ __forceinline__ float sigm(float x) { return 1.f / (1.f + __expf(-x)); }

__device__ __forceinline__ void cpa16(void* dst, const void* src) {
    unsigned d = (unsigned)__cvta_generic_to_shared(dst);
    asm volatile("cp.async.cg.shared.global [%0], [%1], 16;\n" :: "r"(d), "l"(src));
}
#define CPC()  asm volatile("cp.async.commit_group;\n" ::: "memory")
#define CPW(n) asm volatile("cp.async.wait_group %0;\n" :: "n"(n) : "memory")

// ---------------- prep A: embproj = emb @ wih^T + bih + bhh (exact fp32) ----------------
__global__ void prep_embproj(const float* __restrict__ emb, const float* __restrict__ wih,
                             const float* __restrict__ bih, const float* __restrict__ bhh,
                             int is_dec)
{
    __shared__ float er[E_];
    int v = blockIdx.x;
    int n = blockIdx.y * 256 + threadIdx.x;
    er[threadIdx.x] = emb[(long)v * E_ + threadIdx.x];
    __syncthreads();
    float s = bih[n] + bhh[n];
    const float* wr = wih + (long)n * E_;
    #pragma unroll 8
    for (int k = 0; k < E_; k++) s += er[k] * wr[k];
    g_embp[is_dec][(long)v * G4 + n] = s;
}

// ---------------- prep B: reorder whh fp16, fc weights, bias tile, zero states, reset bar --
__global__ void prep2(const float* __restrict__ enc_whh, const float* __restrict__ dec_whh,
                      const float* __restrict__ fc_w,    const float* __restrict__ fc_b)
{
    if (blockIdx.x == 0 && threadIdx.x == 0) g_bar = 0u;
    const long NW  = (long)JT_ * 128 * H_;
    const long NFC = (long)V_ * H_;
    const long NB  = 16L * V_;
    const long NS  = (long)B_ * H_;
    const long total = 2 * NW + NFC + NB + 2 * NS;
    for (long i = (long)blockIdx.x * blockDim.x + threadIdx.x; i < total;
         i += (long)gridDim.x * blockDim.x) {
        long r = i;
        if (r < 2 * NW) {
            int ed = (int)(r / NW);
            long l = r % NW;
            int jt = (int)(l / (128L * H_));
            int rr = (int)((l / H_) % 128);
            int k  = (int)(l % H_);
            int g = rr >> 5, hh = rr & 31;
            long n = (long)g * H_ + jt * 32 + hh;
            const float* whh = ed ? dec_whh : enc_whh;
            g_W2[ed][l] = __float2half(whh[n * H_ + k]);
        } else if (r < 2 * NW + NFC) {
            long l = r - 2 * NW;
            g_fcw16[l] = __float2half(fc_w[l]);
        } else if (r < 2 * NW + NFC + NB) {
            long l = r - 2 * NW - NFC;
            g_biasfc[l] = fc_b[l % V_];
        } else {
            long l = r - 2 * NW - NFC - NB;
            if (l < NS) g_hf[0][l] = __float2half(0.f);
            else        g_c[0][l - NS] = 0.f;
        }
    }
}

// ---------------- persistent kernel: all 255 LSTM steps, W resident in SMEM ----------------
// CTA (bt, jt): batch rows bt*128..+127, h-dims jt*32..+31 (x4 gates = 128 gate rows).
// Cross-CTA state (h) flows exclusively through cp.async.cg (L2), so the atomic-counter
// grid barrier + __threadfence is a sufficient coherence protocol. c is CTA-private.
__global__ __launch_bounds__(256, 1) void seq_kernel(
    const int* __restrict__ src, const int* __restrict__ tgt)
{
    extern __shared__ __align__(16) char smem[];
    __half* Ws  = (__half*)smem;                           // [128 gate-row][LDH k] resident
    __half* hb0 = (__half*)(smem + WBYTES);                // h chunk buffers (overlap epilogue)
    __half* hb1 = (__half*)(smem + WBYTES + 128 * LDW * 2);
    float*  xs   = (float*)(smem + WBYTES);                // [128 b][132 j]
    float*  hout = (float*)(smem + WBYTES + EPI_XS);       // [128 b][36 h]
    __shared__ int tok_s[128];

    const int tid  = threadIdx.x;
    const int warp = tid >> 5;
    const int wj   = warp & 1;          // 2 warps along j (16 each)
    const int wbt  = warp >> 1;         // 4 warps along batch (32 each)
    const int jt   = blockIdx.x & 15;
    const int b0   = (blockIdx.x >> 4) * 128;

    // load resident encoder W tile
    {
        const __half* __restrict__ W = g_W2[0] + (long)jt * 128 * H_;
        for (int i = tid; i < 128 * 64; i += 256) {
            int r = i >> 6, q = i & 63;
            cpa16(Ws + r * LDH + q * 8, W + (long)r * H_ + q * 8);
        }
        CPC(); CPW(0);
        __syncthreads();
    }

    for (int st = 0; st < NSTEP; ++st) {
        const int is_dec = st >= S_;
        const int t   = is_dec ? st - S_ : st;
        const int par = st & 1;
        const int* __restrict__ tok = is_dec ? tgt : src;
        const __half* __restrict__ hg = g_hf[par];

        if (st == S_) {   // swap to decoder weights (CTA-local; prior step fully synced)
            const __half* __restrict__ W = g_W2[1] + (long)jt * 128 * H_;
            for (int i = tid; i < 128 * 64; i += 256) {
                int r = i >> 6, q = i & 63;
                cpa16(Ws + r * LDH + q * 8, W + (long)r * H_ + q * 8);
            }
            CPC(); CPW(0);
            __syncthreads();
        }

        if (tid < 128) tok_s[tid] = tok[(long)(b0 + tid) * 128 + t];

        // prefetch h chunks 0,1
        for (int i = tid; i < 128 * 8; i += 256) {
            int r = i >> 3, q = i & 7;
            cpa16(hb0 + r * LDW + q * 8, hg + (long)(b0 + r) * H_ + q * 8);
        }
        CPC();
        for (int i = tid; i < 128 * 8; i += 256) {
            int r = i >> 3, q = i & 7;
            cpa16(hb1 + r * LDW + q * 8, hg + (long)(b0 + r) * H_ + 64 + q * 8);
        }
        CPC();

        wmma::fragment<wmma::accumulator, 16, 16, 16, float> acc[4][2];
        #pragma unroll
        for (int g = 0; g < 4; g++)
            #pragma unroll
            for (int cb = 0; cb < 2; cb++)
                wmma::fill_fragment(acc[g][cb], 0.f);

        CPW(1);
        __syncthreads();

        #pragma unroll 1
        for (int ch = 0; ch < 8; ch++) {
            const __half* cw = (ch & 1) ? hb1 : hb0;
            #pragma unroll
            for (int kk = 0; kk < 4; kk++) {
                wmma::fragment<wmma::matrix_b, 16, 16, 16, half, wmma::col_major> bf[2];
                #pragma unroll
                for (int cb = 0; cb < 2; cb++)
                    wmma::load_matrix_sync(bf[cb], cw + (wbt * 32 + cb * 16) * LDW + kk * 16, LDW);
                #pragma unroll
                for (int g = 0; g < 4; g++) {
                    wmma::fragment<wmma::matrix_a, 16, 16, 16, half, wmma::row_major> af;
                    wmma::load_matrix_sync(af, Ws + (g * 32 + wj * 16) * LDH + ch * 64 + kk * 16, LDH);
                    wmma::mma_sync(acc[g][0], af, bf[0], acc[g][0]);
                    wmma::mma_sync(acc[g][1], af, bf[1], acc[g][1]);
                }
            }
            __syncthreads();
            if (ch + 2 < 8) {
                __half* nb = (ch & 1) ? hb1 : hb0;
                for (int i = tid; i < 128 * 8; i += 256) {
                    int r = i >> 3, q = i & 7;
                    cpa16(nb + r * LDW + q * 8, hg + (long)(b0 + r) * H_ + (ch + 2) * 64 + q * 8);
                }
                CPC();
            }
            if (ch + 1 < 8) {
                if (ch + 2 < 8) { CPW(1); } else { CPW(0); }
                __syncthreads();
            }
        }

        // -------- epilogue: gather embproj, cell update, write h (fp16) / c (fp32) --------
        __syncthreads();   // chunk buffers free -> reuse as xs
        const float* __restrict__ EP = g_embp[is_dec];
        for (int i = tid; i < 128 * 128; i += 256) {
            int b = i >> 7, j = i & 127;
            int g = j >> 5, hh = j & 31;
            xs[b * 132 + j] = EP[(long)tok_s[b] * G4 + (long)g * H_ + jt * 32 + hh];
        }
        __syncthreads();

        const float* __restrict__ cp_g = g_c[par];
        float* __restrict__ cn_g = g_c[par ^ 1];
        #pragma unroll
        for (int cb = 0; cb < 2; cb++) {
            const int bl = wbt * 32 + cb * 16;
            const long cbase = (long)(b0 + bl) * H_ + jt * 32 + wj * 16;
            wmma::fragment<wmma::accumulator, 16, 16, 16, float> xf[4], cf, hn, cn;
            #pragma unroll
            for (int g = 0; g < 4; g++)
                wmma::load_matrix_sync(xf[g], xs + bl * 132 + g * 32 + wj * 16, 132, wmma::mem_col_major);
            wmma::load_matrix_sync(cf, cp_g + cbase, H_, wmma::mem_col_major);
            #pragma unroll
            for (int e = 0; e < 8; e++) {
                float ig = sigm(acc[0][cb].x[e] + xf[0].x[e]);
                float fg = sigm(acc[1][cb].x[e] + xf[1].x[e]);
                float gg = tanhf(acc[2][cb].x[e] + xf[2].x[e]);
                float og = sigm(acc[3][cb].x[e] + xf[3].x[e]);
                float c2 = fg * cf.x[e] + ig * gg;
                cn.x[e] = c2;
                hn.x[e] = og * tanhf(c2);
            }
            wmma::store_matrix_sync(cn_g + cbase, cn, H_, wmma::mem_col_major);
            wmma::store_matrix_sync(hout + bl * 36 + wj * 16, hn, 36, wmma::mem_col_major);
        }
        __syncthreads();

        __half* __restrict__ hg2 = g_hf[par ^ 1];
        for (int i = tid; i < 128 * 32; i += 256) {
            int b = i >> 5, hh = i & 31;
            __half v = __float2half(hout[b * 36 + hh]);
            hg2[(long)(b0 + b) * H_ + jt * 32 + hh] = v;
            if (is_dec)
                g_hseq[((long)(b0 + b) * (T_ - 1) + t) * H_ + jt * 32 + hh] = v;
        }

        // -------- grid barrier (skip after last step) --------
        if (st + 1 < NSTEP) {
            __syncthreads();
            if (tid == 0) {
                __threadfence();                       // release h writes to L2
                atomicAdd(&g_bar, 1u);
                const unsigned target = (unsigned)(st + 1) * NCTA;
                while (*(volatile unsigned*)&g_bar < target) __nanosleep(64);
            }
            __syncthreads();
        }
    }
}

// ---------------- FC head: logits = h_seq @ fc_w^T + fc_b (fp16 in, fp32 acc) ----------
__global__ __launch_bounds__(256, 1) void fc_kernel()
{
    extern __shared__ __align__(16) char smem[];
    __half* bsm = (__half*)smem;
    __half* ab0 = (__half*)(smem + 128 * LDH * 2);
    __half* ab1 = (__half*)(smem + 128 * LDH * 2 + 128 * LDW * 2);

    const int tid = threadIdx.x;
    const int warp = tid >> 5;
    const int wm = warp >> 2;
    const int wn = warp & 3;
    const long m0 = (long)blockIdx.x * 128;

    for (int i = tid; i < 128 * 64; i += 256) {
        int r = i >> 6, q = i & 63;
        cpa16(bsm + r * LDH + q * 8, g_fcw16 + (long)r * H_ + q * 8);
    }
    for (int i = tid; i < 128 * 8; i += 256) {
        int r = i >> 3, q = i & 7;
        cpa16(ab0 + r * LDW + q * 8, g_hseq + (m0 + r) * H_ + q * 8);
    }
    CPC();
    for (int i = tid; i < 128 * 8; i += 256) {
        int r = i >> 3, q = i & 7;
        cpa16(ab1 + r * LDW + q * 8, g_hseq + (m0 + r) * H_ + 64 + q * 8);
    }
    CPC();
    CPW(1);
    __syncthreads();

    wmma::fragment<wmma::accumulator, 16, 16, 16, float> acc[4][2];
    #pragma unroll
    for (int mm = 0; mm < 4; mm++)
        #pragma unroll
        for (int cb = 0; cb < 2; cb++)
            wmma::load_matrix_sync(acc[mm][cb], g_biasfc + wn * 32 + cb * 16, V_, wmma::mem_row_major);

    #pragma unroll 1
    for (int ch = 0; ch < 8; ch++) {
        const __half* ca = (ch & 1) ? ab1 : ab0;
        #pragma unroll
        for (int kk = 0; kk < 4; kk++) {
            wmma::fragment<wmma::matrix_b, 16, 16, 16, half, wmma::col_major> bf[2];
            #pragma unroll
            for (int cb = 0; cb < 2; cb++)
                wmma::load_matrix_sync(bf[cb], bsm + (wn * 32 + cb * 16) * LDH + ch * 64 + kk * 16, LDH);
            #pragma unroll
            for (int mm = 0; mm < 4; mm++) {
                wmma::fragment<wmma::matrix_a, 16, 16, 16, half, wmma::row_major> af;
                wmma::load_matrix_sync(af, ca + (wm * 64 + mm * 16) * LDW + kk * 16, LDW);
                wmma::mma_sync(acc[mm][0], af, bf[0], acc[mm][0]);
                wmma::mma_sync(acc[mm][1], af, bf[1], acc[mm][1]);
            }
        }
        __syncthreads();
        if (ch + 2 < 8) {
            __half* nb = (ch & 1) ? ab1 : ab0;
            for (int i = tid; i < 128 * 8; i += 256) {
                int r = i >> 3, q = i & 7;
                cpa16(nb + r * LDW + q * 8, g_hseq + (m0 + r) * H_ + (ch + 2) * 64 + q * 8);
            }
            CPC();
        }
        if (ch + 1 < 8) {
            if (ch + 2 < 8) { CPW(1); } else { CPW(0); }
            __syncthreads();
        }
    }

    #pragma unroll
    for (int mm = 0; mm < 4; mm++)
        #pragma unroll
        for (int cb = 0; cb < 2; cb++)
            wmma::store_matrix_sync(g_logits + (m0 + wm * 64 + mm * 16) * V_ + wn * 32 + cb * 16,
                                    acc[mm][cb], V_, wmma::mem_row_major);
}

// ---------------- scatter logits into (B, T, V) with zero row at t=0 ----------------
__global__ void out_kernel(float* __restrict__ out)
{
    const long n4 = (long)B_ * T_ * V_ / 4;
    for (long i = (long)blockIdx.x * blockDim.x + threadIdx.x; i < n4;
         i += (long)gridDim.x * blockDim.x) {
        long e = i * 4;
        int  v  = (int)(e % V_);
        long bt = e / V_;
        int  tt = (int)(bt % T_);
        long b  = bt / T_;
        float4 val;
        if (tt == 0) val = make_float4(0.f, 0.f, 0.f, 0.f);
        else val = *reinterpret_cast<const float4*>(
                       &g_logits[(b * (T_ - 1) + (tt - 1)) * V_ + v]);
        reinterpret_cast<float4*>(out)[i] = val;
    }
}

// ---------------- launch ----------------
extern "C" void kernel_launch(void* const* d_in, const int* in_sizes, int n_in,
                              void* d_out, int out_size)
{
    (void)in_sizes; (void)n_in; (void)out_size;
    const int*   src      = (const int*)  d_in[0];
    const int*   target   = (const int*)  d_in[1];
    const float* emb      = (const float*)d_in[2];
    const float* dec_emb  = (const float*)d_in[3];
    const float* enc_wih  = (const float*)d_in[4];
    const float* enc_whh  = (const float*)d_in[5];
    const float* enc_bih  = (const float*)d_in[6];
    const float* enc_bhh  = (const float*)d_in[7];
    const float* dec_wih  = (const float*)d_in[8];
    const float* dec_whh  = (const float*)d_in[9];
    const float* dec_bih  = (const float*)d_in[10];
    const float* dec_bhh  = (const float*)d_in[11];
    const float* fc_w     = (const float*)d_in[12];
    const float* fc_b     = (const float*)d_in[13];
    float* out = (float*)d_out;

    cudaFuncSetAttribute(seq_kernel, cudaFuncAttributeMaxDynamicSharedMemorySize, SEQ_SMEM);
    cudaFuncSetAttribute(fc_kernel,  cudaFuncAttributeMaxDynamicSharedMemorySize, FC_SMEM);

    prep_embproj<<<dim3(V_, G4 / 256), 256>>>(emb,     enc_wih, enc_bih, enc_bhh, 0);
    prep_embproj<<<dim3(V_, G4 / 256), 256>>>(dec_emb, dec_wih, dec_bih, dec_bhh, 1);
    prep2<<<2048, 256>>>(enc_whh, dec_whh, fc_w, fc_b);

    seq_kernel<<<NCTA, 256, SEQ_SMEM>>>(src, target);

    fc_kernel<<<(B_ * (T_ - 1)) / 128, 256, FC_SMEM>>>();
    out_kernel<<<2048, 256>>>(out);
}

// round 5
// speedup vs baseline: 6.7118x; 1.4621x over previous
#include <cuda_runtime.h>
#include <cuda_fp16.h>
#include <mma.h>
#include <cstdint>

using namespace nvcuda;

#define B_   1024
#define H_   512
#define E_   256
#define S_   128
#define T_   128
#define V_   128
#define G4   2048
#define JT_  16
#define NCTA 128
#define NSTEP (S_ + T_ - 1)     // 255
#define THREADS 512
#define LDH  520                // smem ld (halves) for resident W / fc_w rows
#define LDW  72                 // smem ld (halves) for streamed h chunks
#define CHUNKB (128 * LDW * 2)  // 18432 bytes per 64-k chunk
#define WBYTES (128 * LDH * 2)  // 133120: resident W tile
#define GS_B   (128 * 132 * 4)  // 67584: gate-staging fp32 [128 b][132 j]
#define HO_B   (128 * 36 * 4)   // 18432: hout fp32
#define SEQ_SMEM (WBYTES + GS_B + HO_B)               // 219136 (4 chunks = 73728 overlap GS+HO)
#define FC_SMEM  (128 * LDH * 2 + 2 * 128 * LDW * 2)  // 169984

// ---------------- device scratch ----------------
__device__ __half g_W2[2][JT_ * 128 * H_];           // reordered whh fp16: [jt][g*32+h][k]
__device__ float  g_embp[2][(long)V_ * G4];          // emb @ wih^T + bih + bhh (exact fp32)
__device__ __half g_fcw16[V_ * H_];
__device__ float  g_biasfc[16 * V_];
__device__ __half g_hf[2][(long)B_ * H_];            // hidden fp16, double buffered (cross-CTA via L2)
__device__ __half g_hseq[(long)B_ * (T_ - 1) * H_];
__device__ float  g_logits[(long)B_ * (T_ - 1) * V_];
__device__ unsigned g_bar8[8 * 32];                  // per-b-group barrier counters (128B apart)

__device__ __forceinline__ float sigm(float x) { return 1.f / (1.f + __expf(-x)); }

__device__ __forceinline__ void cpa16(void* dst, const void* src) {
    unsigned d = (unsigned)__cvta_generic_to_shared(dst);
    asm volatile("cp.async.cg.shared.global [%0], [%1], 16;\n" :: "r"(d), "l"(src));
}
#define CPC()  asm volatile("cp.async.commit_group;\n" ::: "memory")
#define CPW(n) asm volatile("cp.async.wait_group %0;\n" :: "n"(n) : "memory")

// copy 64-k chunk ch of this CTA's h tile into smem buffer (all 512 threads)
#define CPCHUNK(buf, ch)                                                          \
    for (int i_ = threadIdx.x; i_ < 128 * 8; i_ += THREADS) {                     \
        int r_ = i_ >> 3, q_ = i_ & 7;                                            \
        cpa16((buf) + r_ * LDW + q_ * 8, hg + (long)(b0 + r_) * H_ + (ch) * 64 + q_ * 8); \
    }

// ---------------- prep A: embproj = emb @ wih^T + bih + bhh (exact fp32) ----------------
__global__ void prep_embproj(const float* __restrict__ emb, const float* __restrict__ wih,
                             const float* __restrict__ bih, const float* __restrict__ bhh,
                             int is_dec)
{
    __shared__ float er[E_];
    int v = blockIdx.x;
    int n = blockIdx.y * 256 + threadIdx.x;
    er[threadIdx.x] = emb[(long)v * E_ + threadIdx.x];
    __syncthreads();
    float s = bih[n] + bhh[n];
    const float* wr = wih + (long)n * E_;
    #pragma unroll 8
    for (int k = 0; k < E_; k++) s += er[k] * wr[k];
    g_embp[is_dec][(long)v * G4 + n] = s;
}

// ---------------- prep B: reorder whh fp16, fc weights, bias tile, zero h0, reset bars ----
__global__ void prep2(const float* __restrict__ enc_whh, const float* __restrict__ dec_whh,
                      const float* __restrict__ fc_w,    const float* __restrict__ fc_b)
{
    if (blockIdx.x == 0 && threadIdx.x < 8 * 32) g_bar8[threadIdx.x] = 0u;
    const long NW  = (long)JT_ * 128 * H_;
    const long NFC = (long)V_ * H_;
    const long NB  = 16L * V_;
    const long NS  = (long)B_ * H_;
    const long total = 2 * NW + NFC + NB + NS;
    for (long i = (long)blockIdx.x * blockDim.x + threadIdx.x; i < total;
         i += (long)gridDim.x * blockDim.x) {
        long r = i;
        if (r < 2 * NW) {
            int ed = (int)(r / NW);
            long l = r % NW;
            int jt = (int)(l / (128L * H_));
            int rr = (int)((l / H_) % 128);
            int k  = (int)(l % H_);
            int g = rr >> 5, hh = rr & 31;
            long n = (long)g * H_ + jt * 32 + hh;
            const float* whh = ed ? dec_whh : enc_whh;
            g_W2[ed][l] = __float2half(whh[n * H_ + k]);
        } else if (r < 2 * NW + NFC) {
            long l = r - 2 * NW;
            g_fcw16[l] = __float2half(fc_w[l]);
        } else if (r < 2 * NW + NFC + NB) {
            long l = r - 2 * NW - NFC;
            g_biasfc[l] = fc_b[l % V_];
        } else {
            long l = r - 2 * NW - NFC - NB;
            g_hf[0][l] = __float2half(0.f);
        }
    }
}

// ---------------- persistent kernel: all 255 LSTM steps ----------------
// CTA (bt, jt): batch rows bt*128..+127, h-dims jt*32..+31 (x4 gates = 128 gate rows).
// 16 warps: wk = warp>>3 splits K (0: k<256, 1: k>=256); (wj, wbt) tile 16j x 32b x 2cb.
// c state lives in wk=0 registers for the whole sequence. Cross-CTA h flows via L2
// (STG -> fence -> per-b-group barrier -> cp.async.cg).
__global__ __launch_bounds__(THREADS, 1) void seq_kernel(
    const int* __restrict__ src, const int* __restrict__ tgt)
{
    extern __shared__ __align__(16) char smem[];
    __half* Ws = (__half*)smem;                       // [128 gate-row][LDH k] resident
    __half* hb[4];
    #pragma unroll
    for (int i = 0; i < 4; i++) hb[i] = (__half*)(smem + WBYTES + i * CHUNKB);
    float* GS   = (float*)(smem + WBYTES);            // [128 b][132 j] gate staging (aliases hb)
    float* hout = (float*)(smem + WBYTES + GS_B);     // [128 b][36 h]
    __shared__ int tok_s[128];

    const int tid  = threadIdx.x;
    const int warp = tid >> 5;
    const int wk   = warp >> 3;         // K half
    const int wj   = warp & 1;          // j sub-tile (16)
    const int wbt  = (warp >> 1) & 3;   // batch sub-tile (32)
    const int jt   = blockIdx.x & 15;
    const int b0   = (blockIdx.x >> 4) * 128;
    const int btg  = blockIdx.x >> 4;   // barrier group

    // resident encoder W tile
    {
        const __half* __restrict__ W = g_W2[0] + (long)jt * 128 * H_;
        for (int i = tid; i < 128 * 64; i += THREADS) {
            int r = i >> 6, q = i & 63;
            cpa16(Ws + r * LDH + q * 8, W + (long)r * H_ + q * 8);
        }
        CPC(); CPW(0);
        __syncthreads();
    }

    // persistent cell state (wk=0 warps only use it)
    wmma::fragment<wmma::accumulator, 16, 16, 16, float> cfr[2];
    wmma::fill_fragment(cfr[0], 0.f);
    wmma::fill_fragment(cfr[1], 0.f);

    for (int st = 0; st < NSTEP; ++st) {
        const int is_dec = st >= S_;
        const int t   = is_dec ? st - S_ : st;
        const int par = st & 1;
        const int* __restrict__ tok = is_dec ? tgt : src;
        const __half* __restrict__ hg = g_hf[par];

        if (st == S_) {   // swap to decoder weights (CTA-local)
            const __half* __restrict__ W = g_W2[1] + (long)jt * 128 * H_;
            for (int i = tid; i < 128 * 64; i += THREADS) {
                int r = i >> 6, q = i & 63;
                cpa16(Ws + r * LDH + q * 8, W + (long)r * H_ + q * 8);
            }
            CPC(); CPW(0);
            __syncthreads();
        }

        if (tid < 128) tok_s[tid] = tok[(long)(b0 + tid) * 128 + t];

        // prologue: pair0 = chunks {0,4}, pair1 = {1,5}
        CPCHUNK(hb[0], 0); CPCHUNK(hb[2], 4); CPC();
        CPCHUNK(hb[1], 1); CPCHUNK(hb[3], 5); CPC();

        wmma::fragment<wmma::accumulator, 16, 16, 16, float> acc[4][2];
        #pragma unroll
        for (int g = 0; g < 4; g++) {
            wmma::fill_fragment(acc[g][0], 0.f);
            wmma::fill_fragment(acc[g][1], 0.f);
        }

        #pragma unroll 1
        for (int c = 0; c < 4; c++) {
            if (c < 3) { CPW(1); } else { CPW(0); }
            __syncthreads();
            const __half* cw = hb[2 * wk + (c & 1)];
            const int ch = wk * 4 + c;           // this warp's K chunk
            #pragma unroll
            for (int kk = 0; kk < 4; kk++) {
                wmma::fragment<wmma::matrix_b, 16, 16, 16, half, wmma::col_major> bf[2];
                #pragma unroll
                for (int cb = 0; cb < 2; cb++)
                    wmma::load_matrix_sync(bf[cb], cw + (wbt * 32 + cb * 16) * LDW + kk * 16, LDW);
                #pragma unroll
                for (int g = 0; g < 4; g++) {
                    wmma::fragment<wmma::matrix_a, 16, 16, 16, half, wmma::row_major> af;
                    wmma::load_matrix_sync(af, Ws + (g * 32 + wj * 16) * LDH + ch * 64 + kk * 16, LDH);
                    wmma::mma_sync(acc[g][0], af, bf[0], acc[g][0]);
                    wmma::mma_sync(acc[g][1], af, bf[1], acc[g][1]);
                }
            }
            __syncthreads();
            if (c + 2 < 4) {
                CPCHUNK(hb[c & 1], c + 2);
                CPCHUNK(hb[2 + (c & 1)], 4 + c + 2);
                CPC();
            }
        }

        // -------- epilogue --------
        // wk=1 warps dump partial sums into GS (aliases freed hb region)
        if (wk == 1) {
            #pragma unroll
            for (int g = 0; g < 4; g++)
                #pragma unroll
                for (int cb = 0; cb < 2; cb++)
                    wmma::store_matrix_sync(GS + (wbt * 32 + cb * 16) * 132 + g * 32 + wj * 16,
                                            acc[g][cb], 132, wmma::mem_col_major);
        }
        __syncthreads();

        // all threads: GS += embproj gather (vectorized)
        const float* __restrict__ EP = g_embp[is_dec];
        for (int i = tid; i < 128 * 32; i += THREADS) {
            int b = i >> 5, j4 = (i & 31) * 4;
            int g = j4 >> 5, hh = j4 & 31;
            const float4 ev = *reinterpret_cast<const float4*>(
                &EP[(long)tok_s[b] * G4 + (long)g * H_ + jt * 32 + hh]);
            float4* gp = reinterpret_cast<float4*>(&GS[b * 132 + j4]);
            float4 gv = *gp;
            gv.x += ev.x; gv.y += ev.y; gv.z += ev.z; gv.w += ev.w;
            *gp = gv;
        }
        __syncthreads();

        // wk=0 warps: combine + cell update (c in registers), stage h
        if (wk == 0) {
            #pragma unroll
            for (int cb = 0; cb < 2; cb++) {
                const int bl = wbt * 32 + cb * 16;
                wmma::fragment<wmma::accumulator, 16, 16, 16, float> xf, hn;
                #pragma unroll
                for (int g = 0; g < 4; g++) {
                    wmma::load_matrix_sync(xf, GS + bl * 132 + g * 32 + wj * 16, 132, wmma::mem_col_major);
                    #pragma unroll
                    for (int e = 0; e < 8; e++) acc[g][cb].x[e] += xf.x[e];
                }
                #pragma unroll
                for (int e = 0; e < 8; e++) {
                    float ig = sigm(acc[0][cb].x[e]);
                    float fg = sigm(acc[1][cb].x[e]);
                    float gg = tanhf(acc[2][cb].x[e]);
                    float og = sigm(acc[3][cb].x[e]);
                    float c2 = fg * cfr[cb].x[e] + ig * gg;
                    cfr[cb].x[e] = c2;
                    hn.x[e] = og * tanhf(c2);
                }
                wmma::store_matrix_sync(hout + bl * 36 + wj * 16, hn, 36, wmma::mem_col_major);
            }
        }
        __syncthreads();

        // all threads: write h (fp16) to global (+ hseq if decoder)
        __half* __restrict__ hg2 = g_hf[par ^ 1];
        for (int i = tid; i < 128 * 32; i += THREADS) {
            int b = i >> 5, hh = i & 31;
            __half v = __float2half(hout[b * 36 + hh]);
            hg2[(long)(b0 + b) * H_ + jt * 32 + hh] = v;
            if (is_dec)
                g_hseq[((long)(b0 + b) * (T_ - 1) + t) * H_ + jt * 32 + hh] = v;
        }

        // -------- per-b-group barrier (16 CTAs) --------
        if (st + 1 < NSTEP) {
            __threadfence();                      // release h writes (all threads)
            __syncthreads();
            if (tid == 0) {
                atomicAdd(&g_bar8[btg * 32], 1u);
                const unsigned target = (unsigned)(st + 1) * 16u;
                while (*(volatile unsigned*)&g_bar8[btg * 32] < target) __nanosleep(64);
            }
            __syncthreads();
        }
    }
}

// ---------------- FC head: logits = h_seq @ fc_w^T + fc_b (fp16 in, fp32 acc) ----------
__global__ __launch_bounds__(256, 1) void fc_kernel()
{
    extern __shared__ __align__(16) char smem[];
    __half* bsm = (__half*)smem;
    __half* ab0 = (__half*)(smem + 128 * LDH * 2);
    __half* ab1 = (__half*)(smem + 128 * LDH * 2 + 128 * LDW * 2);

    const int tid = threadIdx.x;
    const int warp = tid >> 5;
    const int wm = warp >> 2;
    const int wn = warp & 3;
    const long m0 = (long)blockIdx.x * 128;

    for (int i = tid; i < 128 * 64; i += 256) {
        int r = i >> 6, q = i & 63;
        cpa16(bsm + r * LDH + q * 8, g_fcw16 + (long)r * H_ + q * 8);
    }
    for (int i = tid; i < 128 * 8; i += 256) {
        int r = i >> 3, q = i & 7;
        cpa16(ab0 + r * LDW + q * 8, g_hseq + (m0 + r) * H_ + q * 8);
    }
    CPC();
    for (int i = tid; i < 128 * 8; i += 256) {
        int r = i >> 3, q = i & 7;
        cpa16(ab1 + r * LDW + q * 8, g_hseq + (m0 + r) * H_ + 64 + q * 8);
    }
    CPC();
    CPW(1);
    __syncthreads();

    wmma::fragment<wmma::accumulator, 16, 16, 16, float> acc[4][2];
    #pragma unroll
    for (int mm = 0; mm < 4; mm++)
        #pragma unroll
        for (int cb = 0; cb < 2; cb++)
            wmma::load_matrix_sync(acc[mm][cb], g_biasfc + wn * 32 + cb * 16, V_, wmma::mem_row_major);

    #pragma unroll 1
    for (int ch = 0; ch < 8; ch++) {
        const __half* ca = (ch & 1) ? ab1 : ab0;
        #pragma unroll
        for (int kk = 0; kk < 4; kk++) {
            wmma::fragment<wmma::matrix_b, 16, 16, 16, half, wmma::col_major> bf[2];
            #pragma unroll
            for (int cb = 0; cb < 2; cb++)
                wmma::load_matrix_sync(bf[cb], bsm + (wn * 32 + cb * 16) * LDH + ch * 64 + kk * 16, LDH);
            #pragma unroll
            for (int mm = 0; mm < 4; mm++) {
                wmma::fragment<wmma::matrix_a, 16, 16, 16, half, wmma::row_major> af;
                wmma::load_matrix_sync(af, ca + (wm * 64 + mm * 16) * LDW + kk * 16, LDW);
                wmma::mma_sync(acc[mm][0], af, bf[0], acc[mm][0]);
                wmma::mma_sync(acc[mm][1], af, bf[1], acc[mm][1]);
            }
        }
        __syncthreads();
        if (ch + 2 < 8) {
            __half* nb = (ch & 1) ? ab1 : ab0;
            for (int i = tid; i < 128 * 8; i += 256) {
                int r = i >> 3, q = i & 7;
                cpa16(nb + r * LDW + q * 8, g_hseq + (m0 + r) * H_ + (ch + 2) * 64 + q * 8);
            }
            CPC();
        }
        if (ch + 1 < 8) {
            if (ch + 2 < 8) { CPW(1); } else { CPW(0); }
            __syncthreads();
        }
    }

    #pragma unroll
    for (int mm = 0; mm < 4; mm++)
        #pragma unroll
        for (int cb = 0; cb < 2; cb++)
            wmma::store_matrix_sync(g_logits + (m0 + wm * 64 + mm * 16) * V_ + wn * 32 + cb * 16,
                                    acc[mm][cb], V_, wmma::mem_row_major);
}

// ---------------- scatter logits into (B, T, V) with zero row at t=0 ----------------
__global__ void out_kernel(float* __restrict__ out)
{
    const long n4 = (long)B_ * T_ * V_ / 4;
    for (long i = (long)blockIdx.x * blockDim.x + threadIdx.x; i < n4;
         i += (long)gridDim.x * blockDim.x) {
        long e = i * 4;
        int  v  = (int)(e % V_);
        long bt = e / V_;
        int  tt = (int)(bt % T_);
        long b  = bt / T_;
        float4 val;
        if (tt == 0) val = make_float4(0.f, 0.f, 0.f, 0.f);
        else val = *reinterpret_cast<const float4*>(
                       &g_logits[(b * (T_ - 1) + (tt - 1)) * V_ + v]);
        reinterpret_cast<float4*>(out)[i] = val;
    }
}

// ---------------- launch ----------------
extern "C" void kernel_launch(void* const* d_in, const int* in_sizes, int n_in,
                              void* d_out, int out_size)
{
    (void)in_sizes; (void)n_in; (void)out_size;
    const int*   src      = (const int*)  d_in[0];
    const int*   target   = (const int*)  d_in[1];
    const float* emb      = (const float*)d_in[2];
    const float* dec_emb  = (const float*)d_in[3];
    const float* enc_wih  = (const float*)d_in[4];
    const float* enc_whh  = (const float*)d_in[5];
    const float* enc_bih  = (const float*)d_in[6];
    const float* enc_bhh  = (const float*)d_in[7];
    const float* dec_wih  = (const float*)d_in[8];
    const float* dec_whh  = (const float*)d_in[9];
    const float* dec_bih  = (const float*)d_in[10];
    const float* dec_bhh  = (const float*)d_in[11];
    const float* fc_w     = (const float*)d_in[12];
    const float* fc_b     = (const float*)d_in[13];
    float* out = (float*)d_out;

    cudaFuncSetAttribute(seq_kernel, cudaFuncAttributeMaxDynamicSharedMemorySize, SEQ_SMEM);
    cudaFuncSetAttribute(fc_kernel,  cudaFuncAttributeMaxDynamicSharedMemorySize, FC_SMEM);

    prep_embproj<<<dim3(V_, G4 / 256), 256>>>(emb,     enc_wih, enc_bih, enc_bhh, 0);
    prep_embproj<<<dim3(V_, G4 / 256), 256>>>(dec_emb, dec_wih, dec_bih, dec_bhh, 1);
    prep2<<<2048, 256>>>(enc_whh, dec_whh, fc_w, fc_b);

    seq_kernel<<<NCTA, THREADS, SEQ_SMEM>>>(src, target);

    fc_kernel<<<(B_ * (T_ - 1)) / 128, 256, FC_SMEM>>>();
    out_kernel<<<2048, 256>>>(out);
}